// round 5
// baseline (speedup 1.0000x reference)
#include <cuda_runtime.h>
#include <cuda_bf16.h>
#include <cstdint>

#define DEPTH_DIM 256
#define CAP       16             // points per pixel (lambda ~ 1.1; P(overflow) ~ 1e-10)
#define MAX_PIX   (1 << 19)      // up to 512K pixels

__device__ int   g_cnt[MAX_PIX];              // zero-init at load; self-reset each launch
__device__ uint2 g_bin[MAX_PIX * CAP];        // {depth, na2 bits}   (~67 MB)

__device__ __forceinline__ float ex2_fast(float x) {
    float y;
    asm("ex2.approx.ftz.f32 %0, %1;" : "=f"(y) : "f"(x));
    return y;
}

// ---------------------------------------------------------------------------
// K1: bin points by pixel; precompute the exponent coefficient na2 = C / sigma^2
//     (C = -0.5 * h^2 * log2(e), h = 6/255) so the hot loop has no division.
// ---------------------------------------------------------------------------
__global__ void bin_kernel(const int2* __restrict__ pos,
                           const int*  __restrict__ depth,
                           const float* __restrict__ conf,
                           const int*  __restrict__ pW, int npts) {
    int i = blockIdx.x * blockDim.x + threadIdx.x;
    if (i >= npts) return;
    int W = __ldg(pW);
    int2 uv = __ldg(&pos[i]);
    int lin = uv.y * W + uv.x;
    int slot = atomicAdd(&g_cnt[lin], 1);
    if (slot < CAP) {
        const float C = -0.5f * (6.0f / 255.0f) * (6.0f / 255.0f) * 1.4426950408889634f;
        float sigma = __ldg(&conf[i]);
        uint2 v;
        v.x = (unsigned)__ldg(&depth[i]);
        v.y = __float_as_uint(C / (sigma * sigma));
        g_bin[lin * CAP + slot] = v;
    }
}

// ---------------------------------------------------------------------------
// K2: fused accumulate + transposed write (R2-proven structure).
//   Block = 32 consecutive pixels, 8 warps; warp w owns pixels 4w..4w+3 and
//   loops each pixel's slab points directly from global (broadcast loads).
//   Lane L owns depths d = L + 32m; smem tile stride 33 -> conflict-free for
//   both the column store and the row read. No smem staging, no skip-scan.
//   Counters reset after read: zero at entry/exit of every replay.
// ---------------------------------------------------------------------------
__global__ void fused_kernel(float* __restrict__ out, int HW) {
    __shared__ float tile[DEPTH_DIM][33];
    int tid  = threadIdx.x;
    int lane = tid & 31;
    int w    = tid >> 5;
    int pBase = blockIdx.x * 32;

#pragma unroll
    for (int jj = 0; jj < 4; ++jj) {
        int p = pBase + w * 4 + jj;
        float acc[8] = {0.f, 0.f, 0.f, 0.f, 0.f, 0.f, 0.f, 0.f};
        if (p < HW) {
            int cnt = min(g_cnt[p], CAP);
            if (lane == 0) g_cnt[p] = 0;             // self-reset for next replay
            const uint2* __restrict__ slab = g_bin + (size_t)p * CAP;
            for (int t = 0; t < cnt; ++t) {
                uint2 v = slab[t];                   // warp-broadcast 8B load
                int   pd  = (int)v.x;
                float na2 = __uint_as_float(v.y);

                float g[8];
                float s = 0.0f;
#pragma unroll
                for (int m = 0; m < 8; ++m) {
                    int d = lane + 32 * m;
                    int k = d - pd - (d > pd);       // dup k=0 at d=pd,pd+1 (matches ref)
                    float kf = (float)k;
                    g[m] = ex2_fast(na2 * kf * kf);
                    s = fmaf(g[m], g[m], s);
                }
#pragma unroll
                for (int o = 16; o > 0; o >>= 1)
                    s += __shfl_xor_sync(0xffffffffu, s, o);
                float inv = rsqrtf(s);               // s >= 1 (k=0 term), no eps clamp
#pragma unroll
                for (int m = 0; m < 8; ++m)
                    acc[m] = fmaf(g[m], inv, acc[m]);
            }
        }
        // column j = w*4+jj; bank = (lane + j) % 32 -> conflict-free
#pragma unroll
        for (int m = 0; m < 8; ++m)
            tile[lane + 32 * m][w * 4 + jj] = acc[m];
    }
    __syncthreads();

    // coalesced output: each warp writes 32 consecutive pixels per depth row
    int p = pBase + lane;
    if (p < HW) {
#pragma unroll
        for (int m = 0; m < 32; ++m) {
            int d = w + m * 8;
            out[(size_t)d * HW + p] = tile[d][lane];
        }
    }
}

// ---------------------------------------------------------------------------
// Launch
// ---------------------------------------------------------------------------
extern "C" void kernel_launch(void* const* d_in, const int* in_sizes, int n_in,
                              void* d_out, int out_size) {
    const int2*  pos   = (const int2*)d_in[0];   // [N,2] int32 (u=x, v=y)
    const int*   depth = (const int*)d_in[1];    // [N,1] int32
    const float* conf  = (const float*)d_in[2];  // [N,1] float32
    const int*   pW    = (const int*)d_in[4];    // feat_w scalar

    int npts = in_sizes[1];
    int HW   = out_size / DEPTH_DIM;

    bin_kernel<<<(npts + 255) / 256, 256>>>(pos, depth, conf, pW, npts);
    fused_kernel<<<(HW + 31) / 32, 256>>>((float*)d_out, HW);
}

// round 6
// speedup vs baseline: 2.7274x; 2.7274x over previous
#include <cuda_runtime.h>
#include <cuda_bf16.h>
#include <cstdint>

#define DEPTH_DIM 256
#define CAP       16             // slots per pixel; P(Poisson(1.11) > 16) ~ 1e-13
#define MAX_PIX   (1 << 19)      // up to 512K pixels

__device__ int   g_cnt[MAX_PIX];              // zero-init at load; self-reset each launch
__device__ uint2 g_bin[MAX_PIX * CAP];        // {depth, na2 bits}

__device__ __forceinline__ float ex2_fast(float x) {
    float y;
    asm("ex2.approx.ftz.f32 %0, %1;" : "=f"(y) : "f"(x));
    return y;
}

// ---------------------------------------------------------------------------
// K1: bin points by pixel; precompute na2 = C / sigma^2 so the hot loop has
//     no division.  (C = -0.5 * h^2 * log2(e), h = 6/255)
// ---------------------------------------------------------------------------
__global__ void bin_kernel(const int2* __restrict__ pos,
                           const int*  __restrict__ depth,
                           const float* __restrict__ conf,
                           const int*  __restrict__ pW, int npts) {
    int i = blockIdx.x * blockDim.x + threadIdx.x;
    if (i >= npts) return;
    int W = __ldg(pW);
    int2 uv = __ldg(&pos[i]);
    int lin = uv.y * W + uv.x;
    int slot = atomicAdd(&g_cnt[lin], 1);
    if (slot < CAP) {
        const float C = -0.5f * (6.0f / 255.0f) * (6.0f / 255.0f) * 1.4426950408889634f;
        float sigma = __ldg(&conf[i]);
        uint2 v;
        v.x = (unsigned)__ldg(&depth[i]);
        v.y = __float_as_uint(C / (sigma * sigma));
        g_bin[lin * CAP + slot] = v;
    }
}

// ---------------------------------------------------------------------------
// K2: fused accumulate + transposed write.
//   Block = 32 consecutive pixels -> its 32 slabs are one CONTIGUOUS 4KB
//   region of g_bin. Stage it with one coalesced burst (256 thr x 16B), and
//   the 32 counters with one 128B burst; reset counters during staging.
//   Then: warp w owns pixels 4w..4w+3; all hot-loop reads are smem
//   broadcasts. Lane L owns depths d = L + 32m; tile stride 33 keeps both
//   the column store and the row read conflict-free.
// ---------------------------------------------------------------------------
__global__ void fused_kernel(float* __restrict__ out, int HW) {
    __shared__ float tile[DEPTH_DIM][33];
    __shared__ uint2 spts[32][CAP];            // 4KB
    __shared__ int   scnt[32];

    int tid  = threadIdx.x;
    int lane = tid & 31;
    int w    = tid >> 5;
    int pBase = blockIdx.x * 32;

    // stage counters (and reset them for the next graph replay)
    if (tid < 32) {
        int p = pBase + tid;
        int c = 0;
        if (p < HW) {
            c = min(g_cnt[p], CAP);
            g_cnt[p] = 0;
        }
        scnt[tid] = c;
    }
    // stage the block's contiguous 4KB slab region: 256 threads x 16B
    {
        const uint4* src = reinterpret_cast<const uint4*>(g_bin + (size_t)pBase * CAP);
        uint4* dst = reinterpret_cast<uint4*>(&spts[0][0]);
        dst[tid] = src[tid];                   // 32*CAP*8B / 16B = 256 loads exactly
    }
    __syncthreads();

    #pragma unroll
    for (int jj = 0; jj < 4; ++jj) {
        int pl = w * 4 + jj;                   // pixel-in-block 0..31
        int cnt = scnt[pl];
        float acc[8] = {0.f, 0.f, 0.f, 0.f, 0.f, 0.f, 0.f, 0.f};
        for (int t = 0; t < cnt; ++t) {
            uint2 v = spts[pl][t];             // smem broadcast
            int   pd  = (int)v.x;
            float na2 = __uint_as_float(v.y);

            float g[8];
            float s = 0.0f;
            #pragma unroll
            for (int m = 0; m < 8; ++m) {
                int d = lane + 32 * m;
                int k = d - pd - (d > pd);     // dup k=0 at d=pd,pd+1 (matches ref)
                float kf = (float)k;
                g[m] = ex2_fast(na2 * kf * kf);
                s = fmaf(g[m], g[m], s);
            }
            #pragma unroll
            for (int o = 16; o > 0; o >>= 1)
                s += __shfl_xor_sync(0xffffffffu, s, o);
            float inv = rsqrtf(s);             // s >= 1 (k=0 term), no eps clamp
            #pragma unroll
            for (int m = 0; m < 8; ++m)
                acc[m] = fmaf(g[m], inv, acc[m]);
        }
        // column pl: bank = (lane + pl) % 32 -> conflict-free
        #pragma unroll
        for (int m = 0; m < 8; ++m)
            tile[lane + 32 * m][pl] = acc[m];
    }
    __syncthreads();

    // coalesced output: each warp writes 32 consecutive pixels per depth row
    int p = pBase + lane;
    if (p < HW) {
        #pragma unroll
        for (int m = 0; m < 32; ++m) {
            int d = w + m * 8;
            out[(size_t)d * HW + p] = tile[d][lane];
        }
    }
}

// ---------------------------------------------------------------------------
// Launch
// ---------------------------------------------------------------------------
extern "C" void kernel_launch(void* const* d_in, const int* in_sizes, int n_in,
                              void* d_out, int out_size) {
    const int2*  pos   = (const int2*)d_in[0];   // [N,2] int32 (u=x, v=y)
    const int*   depth = (const int*)d_in[1];    // [N,1] int32
    const float* conf  = (const float*)d_in[2];  // [N,1] float32
    const int*   pW    = (const int*)d_in[4];    // feat_w scalar

    int npts = in_sizes[1];
    int HW   = out_size / DEPTH_DIM;

    bin_kernel<<<(npts + 255) / 256, 256>>>(pos, depth, conf, pW, npts);
    fused_kernel<<<(HW + 31) / 32, 256>>>((float*)d_out, HW);
}